// round 9
// baseline (speedup 1.0000x reference)
#include <cuda_runtime.h>
#include <cuda_fp16.h>
#include <math.h>

#define BB 16
#define HH 512
#define WW 512
#define NTOT (BB * HH * WW)

#define RAD 10
#define TILE 64
#define SROWS (TILE + 2 * RAD)  // 84
#define GX (WW / TILE)          // 8
#define GY (HH / TILE)          // 8
#define NB (GX * GY * 8)        // 512 blocks (each handles 2 batch images)

// Scratch (no allocation allowed in kernel_launch)
__device__ __half g_f2h[NTOT];   // horizontal distance^2 (<=100), fp16, 8.4MB
__device__ float g_pl[NB];
__device__ float g_pf[NB];
__device__ unsigned g_done = 0;  // last-block counter (self-resetting)

// ---------------------------------------------------------------------------
// K1: one WARP per image row. Each lane: 16 cols -> 16-bit fg mask; neighbor
// bits via 2 shfls; per-col horizontal distance f (clamped to 10: any d>=10
// gives heatmap <= exp(-100/8)=3.7e-6 ~ 0, loss-equivalent) via clz/ffs on a
// 21-bit window. Stores f^2 as fp16 (exact: integer <= 100). The bit-math
// hides under the streaming tgt loads (K1 issue was 15% when mask-only).
// ---------------------------------------------------------------------------
__global__ __launch_bounds__(256) void k1_f2(const float* __restrict__ tgt) {
    const int gid = blockIdx.x * 256 + threadIdx.x;
    const int row = gid >> 5;
    const int lane = gid & 31;
    const float4* p = (const float4*)(tgt + (size_t)row * WW + lane * 16);
    float4 v0 = p[0], v1 = p[1], v2 = p[2], v3 = p[3];

    unsigned m = 0;
    m |= (v0.x > 0.5f) ? 1u << 0 : 0u;
    m |= (v0.y > 0.5f) ? 1u << 1 : 0u;
    m |= (v0.z > 0.5f) ? 1u << 2 : 0u;
    m |= (v0.w > 0.5f) ? 1u << 3 : 0u;
    m |= (v1.x > 0.5f) ? 1u << 4 : 0u;
    m |= (v1.y > 0.5f) ? 1u << 5 : 0u;
    m |= (v1.z > 0.5f) ? 1u << 6 : 0u;
    m |= (v1.w > 0.5f) ? 1u << 7 : 0u;
    m |= (v2.x > 0.5f) ? 1u << 8 : 0u;
    m |= (v2.y > 0.5f) ? 1u << 9 : 0u;
    m |= (v2.z > 0.5f) ? 1u << 10 : 0u;
    m |= (v2.w > 0.5f) ? 1u << 11 : 0u;
    m |= (v3.x > 0.5f) ? 1u << 12 : 0u;
    m |= (v3.y > 0.5f) ? 1u << 13 : 0u;
    m |= (v3.z > 0.5f) ? 1u << 14 : 0u;
    m |= (v3.w > 0.5f) ? 1u << 15 : 0u;

    unsigned left = __shfl_up_sync(0xffffffffu, m, 1);
    unsigned right = __shfl_down_sync(0xffffffffu, m, 1);
    if (lane == 0) left = 0;
    if (lane == 31) right = 0;
    // bits 0..15 = cols base-16..base-1; 16..31 = own; 32..47 = right
    unsigned long long w = (unsigned long long)left |
                           ((unsigned long long)m << 16) |
                           ((unsigned long long)right << 32);

    __half2 hout[8];
#pragma unroll
    for (int j = 0; j < 8; j++) {
        int f2p[2];
#pragma unroll
        for (int u = 0; u < 2; u++) {
            int pcol = 2 * j + u;
            unsigned win = (unsigned)(w >> (pcol + 6)) & 0x1FFFFFu;  // cols p-10..p+10
            unsigned wl = win & 0x7FFu;         // cols p-10..p (bit10 = center)
            int dl = __clz(wl) - 21;            // 0..11 (11 if none)
            unsigned wr = (win >> 10) | 0x800u; // cols p..p+10, sentinel bit 11
            int dr = __ffs((int)wr) - 1;        // 0..11
            int f = min(min(dl, dr), 10);
            f2p[u] = f * f;
        }
        hout[j] = __floats2half2_rn((float)f2p[0], (float)f2p[1]);
    }
    // 32B per lane, coalesced (1KB per row)
    uint4* dst = (uint4*)(g_f2h + (size_t)row * WW + lane * 16);
    dst[0] = *(uint4*)&hout[0];
    dst[1] = *(uint4*)&hout[4];
}

// ---------------------------------------------------------------------------
// K2: per 64x64 tile (x2 batch images per block for single-wave occupancy):
//  1) copy fp16 f^2 halo (84x64) into smem — straight uint4 copy, no unpack
//  2) fully-unrolled 21-tap half2 min-plus with compile-time (di)^2 weights
//     (exact integer arithmetic in fp16, values <= 200); acc init = 100
//     (= sentinel floor; any true d^2 >= 100 -> heatmap ~ 0)
//  3) branch-free epilogue: p=sigmoid(inp), h=exp(-dmin/8); bg-uniform
//     f=0.15p^2, l=0.15(p(p-h))^2; fg px (dmin==0, h=1 exact) rare correction
//  4) shuffle reduce; last block folds the final scalar.
// ---------------------------------------------------------------------------
__global__ __launch_bounds__(256) void k2_main(const float* __restrict__ inp,
                                               float* __restrict__ out) {
    const int tid = threadIdx.x;
    const int tx = tid & 31;  // half2 column pair: cols 2tx, 2tx+1
    const int ty = tid >> 5;  // row group: rows ty*8 .. ty*8+7
    const int j0 = blockIdx.x * TILE;
    const int i0 = blockIdx.y * TILE;

    __shared__ __align__(16) __half2 sf2[SROWS][TILE / 2];  // 10.5 KB
    __shared__ float swF[8];
    __shared__ float swL[8];
    __shared__ int slast;

    float thF = 0.0f, thL = 0.0f;
    const int r0 = ty * 8;

#pragma unroll 1
    for (int sub = 0; sub < 2; sub++) {
        const int b = blockIdx.z + sub * 8;
        __syncthreads();  // previous sub's window reads done before overwrite

        // --- 1) halo copy: 84 rows x 8 uint4 ---
        const uint4 sent = make_uint4(0x56405640u, 0x56405640u, 0x56405640u,
                                      0x56405640u);  // half(100) x8
        for (int e = tid; e < SROWS * 8; e += 256) {
            int rr = e >> 3;
            int c = e & 7;
            int gr = i0 - RAD + rr;
            uint4 v = sent;
            if ((unsigned)gr < HH)
                v = *(const uint4*)(g_f2h + ((size_t)(b * HH + gr)) * WW + j0 + c * 8);
            ((uint4*)&sf2[rr][0])[c] = v;
        }
        __syncthreads();

        // --- 2) dense 21-tap min-plus, compile-time weights ---
        __half2 acc[8];
#pragma unroll
        for (int mm = 0; mm < 8; mm++) acc[mm] = __float2half2_rn(100.0f);
#pragma unroll
        for (int t = 0; t < 28; t++) {
            __half2 v = sf2[r0 + t][tx];
#pragma unroll
            for (int mm = 0; mm < 8; mm++) {
                const int dk = t - mm;
                if (dk >= 0 && dk <= 2 * RAD) {
                    const float wgt = (float)((dk - RAD) * (dk - RAD));
                    acc[mm] = __hmin2(acc[mm], __hadd2(v, __float2half2_rn(wgt)));
                }
            }
        }

        // --- 3) epilogue ---
        const float* ib = inp + ((size_t)(b * HH + i0 + r0)) * WW + j0 + 2 * tx;
        float fsum = 0.0f, lsum = 0.0f;
        float mn = 100.0f;
#pragma unroll
        for (int mm = 0; mm < 8; mm++) {
            float2 x2 = *(const float2*)(ib + (size_t)mm * WW);
            float2 dd = __half22float2(acc[mm]);
            mn = fminf(mn, fminf(dd.x, dd.y));
            float p0 = __fdividef(1.0f, 1.0f + __expf(-x2.x));
            float h0 = __expf(dd.x * -0.125f);
            fsum = fmaf(p0, p0, fsum);
            float t0 = p0 * (p0 - h0);
            lsum = fmaf(t0, t0, lsum);
            float p1 = __fdividef(1.0f, 1.0f + __expf(-x2.y));
            float h1 = __expf(dd.y * -0.125f);
            fsum = fmaf(p1, p1, fsum);
            float t1 = p1 * (p1 - h1);
            lsum = fmaf(t1, t1, lsum);
        }
        thF += 0.15f * fsum;
        thL += 0.15f * lsum;

        if (mn == 0.0f) {  // rare: thread owns >=1 foreground pixel
            for (int mm = 0; mm < 8; mm++) {
                float2 x2 = *(const float2*)(ib + (size_t)mm * WW);
                float2 dd = __half22float2(acc[mm]);
                if (dd.x == 0.0f) {
                    float p = __fdividef(1.0f, 1.0f + __expf(-x2.x));
                    float qq = 1.0f - p;
                    float cf = 0.85f * qq * qq - 0.15f * p * p;
                    thF += cf;
                    thL += qq * qq * cf;
                }
                if (dd.y == 0.0f) {
                    float p = __fdividef(1.0f, 1.0f + __expf(-x2.y));
                    float qq = 1.0f - p;
                    float cf = 0.85f * qq * qq - 0.15f * p * p;
                    thF += cf;
                    thL += qq * qq * cf;
                }
            }
        }
    }

    // --- 4) shuffle reduction (fixed order -> deterministic) ---
#pragma unroll
    for (int off = 16; off > 0; off >>= 1) {
        thF += __shfl_xor_sync(0xffffffffu, thF, off);
        thL += __shfl_xor_sync(0xffffffffu, thL, off);
    }
    if (tx == 0) {
        swF[ty] = thF;
        swL[ty] = thL;
    }
    __syncthreads();

    const int bid = blockIdx.x + GX * (blockIdx.y + GY * blockIdx.z);
    if (tid == 0) {
        float F = 0.0f, Lv = 0.0f;
#pragma unroll
        for (int w = 0; w < 8; w++) {
            F += swF[w];
            Lv += swL[w];
        }
        g_pf[bid] = F;
        g_pl[bid] = Lv;
        __threadfence();
        unsigned old = atomicAdd(&g_done, 1u);
        slast = (old == NB - 1) ? 1 : 0;
    }
    __syncthreads();

    // --- last block: fold final scalar (reuses sf2 as double scratch) ---
    if (slast) {
        __threadfence();
        double* sFd = (double*)&sf2[0][0];
        double* sLd = sFd + 256;
        double f = 0.0, l = 0.0;
        for (int i = tid; i < NB; i += 256) {
            f += (double)g_pf[i];
            l += (double)g_pl[i];
        }
        sFd[tid] = f;
        sLd[tid] = l;
        __syncthreads();
#pragma unroll
        for (int s = 128; s > 0; s >>= 1) {
            if (tid < s) {
                sFd[tid] += sFd[tid + s];
                sLd[tid] += sLd[tid + s];
            }
            __syncthreads();
        }
        if (tid == 0) {
            double n = (double)NTOT;
            double denom = sFd[0] / n + 0.01;
            out[0] = (float)(2.0 * (sLd[0] / n) / denom);
            g_done = 0;  // reset for next graph replay
        }
    }
}

extern "C" void kernel_launch(void* const* d_in, const int* in_sizes, int n_in,
                              void* d_out, int out_size) {
    const float* inp = (const float*)d_in[0];
    const float* tgt = (const float*)d_in[1];
    float* out = (float*)d_out;

    k1_f2<<<(BB * HH * 32) / 256, 256>>>(tgt);
    dim3 g2(GX, GY, 8);  // each block handles batches z and z+8
    k2_main<<<g2, 256>>>(inp, out);
}